// round 4
// baseline (speedup 1.0000x reference)
#include <cuda_runtime.h>

#define B        8
#define KN       768
#define BETA_N   192
#define NCOV     64
#define NPTS     256
#define C_OUT    128
#define HW_OUT   (256*256)
#define C_RES    64
#define HW_RES   (512*512)
#define C_FEAT   192
#define REND_ELEMS (B*C_OUT*NPTS)   // 262144

__device__ float g_unc[B * KN];
__device__ float g_coarse[(size_t)B * KN * C_OUT];
__device__ float g_covfeat[(size_t)B * C_FEAT * NCOV];
__device__ float g_wT[C_FEAT * C_OUT];
__device__ int   g_selidx[B * BETA_N];

// ------------------------------------------------------------------
// Kernel A: grid (113, 8), block 256.
//  x <  96 : uncertainty + cached coarse features (1 warp / point)
//  96..111 : cov-point full feature gather
//  x == 112: (b==0) weight transpose
// ------------------------------------------------------------------
__global__ void unc_kernel(const float* __restrict__ outp,
                           const float* __restrict__ res2,
                           const float* __restrict__ rand_over,
                           const float* __restrict__ rand_cov,
                           const float* __restrict__ weight) {
    int b   = blockIdx.y;
    int bx  = blockIdx.x;
    int tid = threadIdx.x;

    if (bx >= 96) {
        if (bx == 112) {
            if (b != 0) return;
            const float4* w4 = (const float4*)weight;
#pragma unroll
            for (int i = 0; i < 24; i++) {
                int idx = i * 256 + tid;
                int o = idx / 48, rem = idx - o * 48;
                float4 v = __ldg(w4 + idx);
                int cb = rem * 4;
                g_wT[(cb + 0) * C_OUT + o] = v.x;
                g_wT[(cb + 1) * C_OUT + o] = v.y;
                g_wT[(cb + 2) * C_OUT + o] = v.z;
                g_wT[(cb + 3) * C_OUT + o] = v.w;
            }
            return;
        }
        int g = bx - 96;
#pragma unroll
        for (int i = 0; i < 3; i++) {
            int v  = i * 256 + tid;
            int jj = v & 3, c = v >> 2;
            int j  = g * 4 + jj;
            float px = __ldg(rand_cov + ((size_t)b * NCOV + j) * 2 + 0);
            float py = __ldg(rand_cov + ((size_t)b * NCOV + j) * 2 + 1);
            const float* plane;
            int H;
            if (c < C_OUT) { plane = outp + (size_t)(b * C_OUT + c) * HW_OUT; H = 256; }
            else           { plane = res2 + (size_t)(b * C_RES + (c - C_OUT)) * HW_RES; H = 512; }
            float gx = px * (float)H - 0.5f, gy = py * (float)H - 0.5f;
            float xf = floorf(gx), yf = floorf(gy);
            int x0 = (int)xf, y0 = (int)yf;
            float fx = gx - xf, fy = gy - yf;
            float r = 0.0f;
#pragma unroll
            for (int q = 0; q < 4; q++) {
                int xi = x0 + (q & 1), yi = y0 + (q >> 1);
                if (xi >= 0 && xi < H && yi >= 0 && yi < H) {
                    float cf = ((q & 1) ? fx : 1.0f - fx) * ((q >> 1) ? fy : 1.0f - fy);
                    r = fmaf(cf, __ldg(plane + (size_t)yi * H + xi), r);
                }
            }
            g_covfeat[((size_t)b * C_FEAT + c) * NCOV + j] = r;
        }
        return;
    }

    int warp = tid >> 5, lane = tid & 31;
    int p = bx * 8 + warp;

    const float* rnd = rand_over + ((size_t)b * KN + p) * 2;
    float px = rnd[0], py = rnd[1];

    float gx = __fadd_rn(__fmul_rn(px, 256.0f), -0.5f);
    float gy = __fadd_rn(__fmul_rn(py, 256.0f), -0.5f);
    float x0f = floorf(gx), y0f = floorf(gy);
    float wx = __fadd_rn(gx, -x0f);
    float wy = __fadd_rn(gy, -y0f);
    int x0 = (int)x0f, y0 = (int)y0f;

    int   pix[4];
    float vld[4];
#pragma unroll
    for (int j = 0; j < 4; j++) {
        int xi = x0 + (j & 1), yi = y0 + (j >> 1);
        vld[j] = (xi >= 0 && xi < 256 && yi >= 0 && yi < 256) ? 1.0f : 0.0f;
        int cx = min(max(xi, 0), 255), cy = min(max(yi, 0), 255);
        pix[j] = cy * 256 + cx;
    }

    const float* ob = outp + (size_t)b * C_OUT * HW_OUT;
    float vals[16];
#pragma unroll
    for (int j = 0; j < 4; j++)
#pragma unroll
        for (int k = 0; k < 4; k++)
            vals[j * 4 + k] = __ldg(ob + (size_t)(lane + k * 32) * HW_OUT + pix[j]);

    {
        float omx = 1.0f - wx, omy = 1.0f - wy;
        float cw[4] = { omx * omy * vld[0], wx * omy * vld[1],
                        omx * wy  * vld[2], wx * wy  * vld[3] };
        float* cc = g_coarse + ((size_t)b * KN + p) * C_OUT + lane;
#pragma unroll
        for (int k = 0; k < 4; k++) {
            float r = vals[k] * cw[0];
            r = fmaf(vals[4 + k],  cw[1], r);
            r = fmaf(vals[8 + k],  cw[2], r);
            r = fmaf(vals[12 + k], cw[3], r);
            cc[k * 32] = r;
        }
    }

    float m1c[4], m2c[4];
#pragma unroll
    for (int j = 0; j < 4; j++) {
        float m1 = vals[j * 4], m2 = -3.4e38f;
#pragma unroll
        for (int k = 1; k < 4; k++) {
            float v  = vals[j * 4 + k];
            float hi = fmaxf(m1, v), lo = fminf(m1, v);
            m2 = fmaxf(m2, lo);
            m1 = hi;
        }
#pragma unroll
        for (int off = 16; off; off >>= 1) {
            float o1 = __shfl_xor_sync(0xffffffffu, m1, off);
            float o2 = __shfl_xor_sync(0xffffffffu, m2, off);
            float hi = fmaxf(m1, o1), lo = fminf(m1, o1);
            m2 = fmaxf(lo, fmaxf(m2, o2));
            m1 = hi;
        }
        m1c[j] = m1; m2c[j] = m2;
    }

    if (lane == 0) {
        float omx = __fadd_rn(1.0f, -wx);
        float omy = __fadd_rn(1.0f, -wy);
        float v0, t, og0, og1;
        v0 = __fmul_rn(m1c[0], vld[0]); t = __fmul_rn(__fmul_rn(v0, omx), omy); og0 = t;
        v0 = __fmul_rn(m1c[1], vld[1]); t = __fmul_rn(__fmul_rn(v0, wx),  omy); og0 = __fadd_rn(og0, t);
        v0 = __fmul_rn(m1c[2], vld[2]); t = __fmul_rn(__fmul_rn(v0, omx), wy);  og0 = __fadd_rn(og0, t);
        v0 = __fmul_rn(m1c[3], vld[3]); t = __fmul_rn(__fmul_rn(v0, wx),  wy);  og0 = __fadd_rn(og0, t);
        v0 = __fmul_rn(m2c[0], vld[0]); t = __fmul_rn(__fmul_rn(v0, omx), omy); og1 = t;
        v0 = __fmul_rn(m2c[1], vld[1]); t = __fmul_rn(__fmul_rn(v0, wx),  omy); og1 = __fadd_rn(og1, t);
        v0 = __fmul_rn(m2c[2], vld[2]); t = __fmul_rn(__fmul_rn(v0, omx), wy);  og1 = __fadd_rn(og1, t);
        v0 = __fmul_rn(m2c[3], vld[3]); t = __fmul_rn(__fmul_rn(v0, wx),  wy);  og1 = __fadd_rn(og1, t);
        g_unc[b * KN + p] = -__fadd_rn(og0, -og1);
    }
}

// ------------------------------------------------------------------
// Kernel B: hybrid shfl/smem bitonic (stable top-192) + points out
// ------------------------------------------------------------------
__device__ __forceinline__ unsigned long long bstep(unsigned long long v,
                                                    unsigned long long u,
                                                    int t, int k, int j) {
    bool keep_min = (((t & k) == 0) == ((t & j) == 0));
    unsigned long long mn = v < u ? v : u;
    unsigned long long mx = v < u ? u : v;
    return keep_min ? mn : mx;
}

__global__ void sort_kernel(const float* __restrict__ rand_over,
                            const float* __restrict__ rand_cov,
                            float* __restrict__ dout) {
    __shared__ unsigned long long key[1024];
    int b = blockIdx.x;
    int t = threadIdx.x;

    unsigned long long v = ~0ULL;
    if (t < KN) {
        float u = g_unc[b * KN + t];
        unsigned ub = __float_as_uint(u);
        ub = (ub & 0x80000000u) ? ~ub : (ub | 0x80000000u);
        ub = ~ub;
        v = ((unsigned long long)ub << 32) | (unsigned)t;
    }

#pragma unroll
    for (int k = 2; k <= 32; k <<= 1) {
#pragma unroll
        for (int j = k >> 1; j > 0; j >>= 1) {
            unsigned long long u = __shfl_xor_sync(0xffffffffu, v, j);
            v = bstep(v, u, t, k, j);
        }
    }
    for (int k = 64; k <= 1024; k <<= 1) {
        for (int j = k >> 1; j >= 32; j >>= 1) {
            key[t] = v;
            __syncthreads();
            unsigned long long u = key[t ^ j];
            v = bstep(v, u, t, k, j);
            __syncthreads();
        }
#pragma unroll
        for (int j = 16; j > 0; j >>= 1) {
            unsigned long long u = __shfl_xor_sync(0xffffffffu, v, j);
            v = bstep(v, u, t, k, j);
        }
    }

    float* pts = dout + REND_ELEMS;
    if (t < BETA_N) {
        int idx = (int)(v & 0xFFFFFFFFu);
        g_selidx[b * BETA_N + t] = idx;
        pts[((size_t)b * NPTS + t) * 2 + 0] = rand_over[((size_t)b * KN + idx) * 2 + 0];
        pts[((size_t)b * NPTS + t) * 2 + 1] = rand_over[((size_t)b * KN + idx) * 2 + 1];
    } else if (t < NPTS) {
        int j2 = t - BETA_N;
        pts[((size_t)b * NPTS + t) * 2 + 0] = rand_cov[((size_t)b * NCOV + j2) * 2 + 0];
        pts[((size_t)b * NPTS + t) * 2 + 1] = rand_cov[((size_t)b * NCOV + j2) * 2 + 1];
    }
}

// ------------------------------------------------------------------
// Kernel C: rend. grid (16, 8), block 128. smem: fsh[192][16] = 12 KB.
// Thread tile: 4 outputs x 4 points; weights read straight from L1.
// ------------------------------------------------------------------
#define TILE 16
#define SMEM_BYTES (C_FEAT * TILE * 4)

__global__ void rend_kernel(const float* __restrict__ res2,
                            const float* __restrict__ bias,
                            float* __restrict__ dout) {
    extern __shared__ float fsh[];      // [c][p] row = 16 floats (64 B)

    __shared__ int   offB[TILE][4];
    __shared__ float wB[TILE][4];

    int b = blockIdx.y, tile = blockIdx.x;
    bool is_cov = (tile >= 12);
    int tid = threadIdx.x;

    if (!is_cov && tid < TILE) {
        const float* pts = dout + REND_ELEMS + ((size_t)b * NPTS + tile * TILE + tid) * 2;
        float px = pts[0], py = pts[1];
        float gx = px * 512.0f - 0.5f, gy = py * 512.0f - 0.5f;
        float xf = floorf(gx), yf = floorf(gy);
        int x0 = (int)xf, y0 = (int)yf;
        float fx = gx - xf, fy = gy - yf;
#pragma unroll
        for (int j = 0; j < 4; j++) {
            int xi = x0 + (j & 1), yi = y0 + (j >> 1);
            float vv = (xi >= 0 && xi < 512 && yi >= 0 && yi < 512) ? 1.0f : 0.0f;
            offB[tid][j] = min(max(yi, 0), 511) * 512 + min(max(xi, 0), 511);
            wB[tid][j]   = ((j & 1) ? fx : 1.0f - fx) * ((j >> 1) ? fy : 1.0f - fy) * vv;
        }
    }
    __syncthreads();

    if (is_cov) {
        // coalesced copy of precomputed cov features: 192c x 16p
        const float* src = g_covfeat + (size_t)b * C_FEAT * NCOV + (tile - 12) * TILE;
#pragma unroll
        for (int i = 0; i < 24; i++) {
            int v = i * 128 + tid;
            int p = v & 15, c = v >> 4;
            fsh[c * TILE + p] = __ldg(src + c * NCOV + p);
        }
    } else {
        const int* sel = g_selidx + b * BETA_N + tile * TILE;
        // coarse cached: c fast (coalesced 512B per point)
#pragma unroll
        for (int i = 0; i < 16; i++) {
            int v = i * 128 + tid;
            int c = v & 127, p = v >> 7;   // p = i*128+tid >> 7
            fsh[c * TILE + p] = __ldg(g_coarse + ((size_t)b * KN + __ldg(sel + p)) * C_OUT + c);
        }
        // res2 gather: 64c x 16p
#pragma unroll 4
        for (int i = 0; i < 8; i++) {
            int v = i * 128 + tid;
            int p = v & 15, c = v >> 4;
            const float* plane = res2 + (size_t)(b * C_RES + c) * HW_RES;
            float r =        wB[p][0] * __ldg(plane + offB[p][0]);
            r = fmaf(wB[p][1], __ldg(plane + offB[p][1]), r);
            r = fmaf(wB[p][2], __ldg(plane + offB[p][2]), r);
            r = fmaf(wB[p][3], __ldg(plane + offB[p][3]), r);
            fsh[(C_OUT + c) * TILE + p] = r;
        }
    }
    __syncthreads();

    // GEMV: thread = (o_grp = tid&31 -> 4 outputs, pg = tid>>5 -> 4 points)
    int o_grp = tid & 31, pg = tid >> 5;
    const float4* w4 = (const float4*)g_wT;       // [c][o/4]
    const float4* f4 = (const float4*)fsh;        // [c][p/4]

    float4 bv = __ldg((const float4*)bias + o_grp);
    float acc[4][4];
#pragma unroll
    for (int q = 0; q < 4; q++) {
        acc[0][q] = bv.x; acc[1][q] = bv.y; acc[2][q] = bv.z; acc[3][q] = bv.w;
    }

#pragma unroll 4
    for (int c = 0; c < C_FEAT; c++) {
        float4 w = __ldg(w4 + c * 32 + o_grp);    // coalesced, L1-resident
        float4 f = f4[c * 4 + pg];                // warp-broadcast LDS.128
        acc[0][0] = fmaf(w.x, f.x, acc[0][0]);
        acc[0][1] = fmaf(w.x, f.y, acc[0][1]);
        acc[0][2] = fmaf(w.x, f.z, acc[0][2]);
        acc[0][3] = fmaf(w.x, f.w, acc[0][3]);
        acc[1][0] = fmaf(w.y, f.x, acc[1][0]);
        acc[1][1] = fmaf(w.y, f.y, acc[1][1]);
        acc[1][2] = fmaf(w.y, f.z, acc[1][2]);
        acc[1][3] = fmaf(w.y, f.w, acc[1][3]);
        acc[2][0] = fmaf(w.z, f.x, acc[2][0]);
        acc[2][1] = fmaf(w.z, f.y, acc[2][1]);
        acc[2][2] = fmaf(w.z, f.z, acc[2][2]);
        acc[2][3] = fmaf(w.z, f.w, acc[2][3]);
        acc[3][0] = fmaf(w.w, f.x, acc[3][0]);
        acc[3][1] = fmaf(w.w, f.y, acc[3][1]);
        acc[3][2] = fmaf(w.w, f.z, acc[3][2]);
        acc[3][3] = fmaf(w.w, f.w, acc[3][3]);
    }

    float* rp = dout + ((size_t)b * C_OUT + o_grp * 4) * NPTS + tile * TILE + pg * 4;
#pragma unroll
    for (int i = 0; i < 4; i++)
        *(float4*)(rp + (size_t)i * NPTS) =
            make_float4(acc[i][0], acc[i][1], acc[i][2], acc[i][3]);
}

// ------------------------------------------------------------------
extern "C" void kernel_launch(void* const* d_in, const int* in_sizes, int n_in,
                              void* d_out, int out_size) {
    (void)in_sizes; (void)n_in; (void)out_size;
    const float* res2      = (const float*)d_in[1];
    const float* outp      = (const float*)d_in[2];
    const float* rand_over = (const float*)d_in[3];
    const float* rand_cov  = (const float*)d_in[4];
    const float* weight    = (const float*)d_in[5];
    const float* bias      = (const float*)d_in[6];
    float* dout = (float*)d_out;

    unc_kernel<<<dim3(113, B), 256>>>(outp, res2, rand_over, rand_cov, weight);
    sort_kernel<<<B, 1024>>>(rand_over, rand_cov, dout);
    rend_kernel<<<dim3(16, B), 128, SMEM_BYTES>>>(res2, bias, dout);
}

// round 5
// speedup vs baseline: 1.8264x; 1.8264x over previous
#include <cuda_runtime.h>

#define B        8
#define KN       768
#define BETA_N   192
#define NCOV     64
#define NPTS     256
#define C_OUT    128
#define HW_OUT   (256*256)
#define C_RES    64
#define HW_RES   (512*512)
#define C_FEAT   192
#define REND_ELEMS (B*C_OUT*NPTS)   // 262144

__device__ float g_unc[B * KN];
__device__ float g_coarse[(size_t)B * KN * C_OUT];       // [b][pt][c]
__device__ float g_covfeat[(size_t)B * NCOV * C_FEAT];   // [b][pt][c]
__device__ float g_wT[C_FEAT * C_OUT];                   // [c][o]
__device__ int   g_selidx[B * BETA_N];

// ------------------------------------------------------------------
// Kernel A: grid (113, 8), block 256.
//  x <  96 : uncertainty + cached coarse features (1 warp / point)
//  96..111 : cov-point full feature gather ([b][pt][c] layout)
//  x == 112: (b==0) weight transpose
// ------------------------------------------------------------------
__global__ void unc_kernel(const float* __restrict__ outp,
                           const float* __restrict__ res2,
                           const float* __restrict__ rand_over,
                           const float* __restrict__ rand_cov,
                           const float* __restrict__ weight) {
    int b   = blockIdx.y;
    int bx  = blockIdx.x;
    int tid = threadIdx.x;

    if (bx >= 96) {
        if (bx == 112) {
            if (b != 0) return;
            const float4* w4 = (const float4*)weight;
#pragma unroll
            for (int i = 0; i < 24; i++) {
                int idx = i * 256 + tid;
                int o = idx / 48, rem = idx - o * 48;
                float4 v = __ldg(w4 + idx);
                int cb = rem * 4;
                g_wT[(cb + 0) * C_OUT + o] = v.x;
                g_wT[(cb + 1) * C_OUT + o] = v.y;
                g_wT[(cb + 2) * C_OUT + o] = v.z;
                g_wT[(cb + 3) * C_OUT + o] = v.w;
            }
            return;
        }
        // cov gather: 4 points x 192 channels, channel-fast lanes
        int g = bx - 96;
#pragma unroll
        for (int i = 0; i < 3; i++) {
            int v  = i * 256 + tid;          // 0..767
            int jl = v / C_FEAT;             // 0..3
            int c  = v - jl * C_FEAT;        // 0..191
            int j  = g * 4 + jl;
            float px = __ldg(rand_cov + ((size_t)b * NCOV + j) * 2 + 0);
            float py = __ldg(rand_cov + ((size_t)b * NCOV + j) * 2 + 1);
            const float* plane;
            int H;
            if (c < C_OUT) { plane = outp + (size_t)(b * C_OUT + c) * HW_OUT; H = 256; }
            else           { plane = res2 + (size_t)(b * C_RES + (c - C_OUT)) * HW_RES; H = 512; }
            float gx = px * (float)H - 0.5f, gy = py * (float)H - 0.5f;
            float xf = floorf(gx), yf = floorf(gy);
            int x0 = (int)xf, y0 = (int)yf;
            float fx = gx - xf, fy = gy - yf;
            float r = 0.0f;
#pragma unroll
            for (int q = 0; q < 4; q++) {
                int xi = x0 + (q & 1), yi = y0 + (q >> 1);
                if (xi >= 0 && xi < H && yi >= 0 && yi < H) {
                    float cf = ((q & 1) ? fx : 1.0f - fx) * ((q >> 1) ? fy : 1.0f - fy);
                    r = fmaf(cf, __ldg(plane + (size_t)yi * H + xi), r);
                }
            }
            g_covfeat[((size_t)b * NCOV + j) * C_FEAT + c] = r;
        }
        return;
    }

    int warp = tid >> 5, lane = tid & 31;
    int p = bx * 8 + warp;

    const float* rnd = rand_over + ((size_t)b * KN + p) * 2;
    float px = rnd[0], py = rnd[1];

    float gx = __fadd_rn(__fmul_rn(px, 256.0f), -0.5f);
    float gy = __fadd_rn(__fmul_rn(py, 256.0f), -0.5f);
    float x0f = floorf(gx), y0f = floorf(gy);
    float wx = __fadd_rn(gx, -x0f);
    float wy = __fadd_rn(gy, -y0f);
    int x0 = (int)x0f, y0 = (int)y0f;

    int   pix[4];
    float vld[4];
#pragma unroll
    for (int j = 0; j < 4; j++) {
        int xi = x0 + (j & 1), yi = y0 + (j >> 1);
        vld[j] = (xi >= 0 && xi < 256 && yi >= 0 && yi < 256) ? 1.0f : 0.0f;
        int cx = min(max(xi, 0), 255), cy = min(max(yi, 0), 255);
        pix[j] = cy * 256 + cx;
    }

    const float* ob = outp + (size_t)b * C_OUT * HW_OUT;
    float vals[16];
#pragma unroll
    for (int j = 0; j < 4; j++)
#pragma unroll
        for (int k = 0; k < 4; k++)
            vals[j * 4 + k] = __ldg(ob + (size_t)(lane + k * 32) * HW_OUT + pix[j]);

    {
        float omx = 1.0f - wx, omy = 1.0f - wy;
        float cw[4] = { omx * omy * vld[0], wx * omy * vld[1],
                        omx * wy  * vld[2], wx * wy  * vld[3] };
        float* cc = g_coarse + ((size_t)b * KN + p) * C_OUT + lane;
#pragma unroll
        for (int k = 0; k < 4; k++) {
            float r = vals[k] * cw[0];
            r = fmaf(vals[4 + k],  cw[1], r);
            r = fmaf(vals[8 + k],  cw[2], r);
            r = fmaf(vals[12 + k], cw[3], r);
            cc[k * 32] = r;
        }
    }

    float m1c[4], m2c[4];
#pragma unroll
    for (int j = 0; j < 4; j++) {
        float m1 = vals[j * 4], m2 = -3.4e38f;
#pragma unroll
        for (int k = 1; k < 4; k++) {
            float v  = vals[j * 4 + k];
            float hi = fmaxf(m1, v), lo = fminf(m1, v);
            m2 = fmaxf(m2, lo);
            m1 = hi;
        }
#pragma unroll
        for (int off = 16; off; off >>= 1) {
            float o1 = __shfl_xor_sync(0xffffffffu, m1, off);
            float o2 = __shfl_xor_sync(0xffffffffu, m2, off);
            float hi = fmaxf(m1, o1), lo = fminf(m1, o1);
            m2 = fmaxf(lo, fmaxf(m2, o2));
            m1 = hi;
        }
        m1c[j] = m1; m2c[j] = m2;
    }

    if (lane == 0) {
        float omx = __fadd_rn(1.0f, -wx);
        float omy = __fadd_rn(1.0f, -wy);
        float v0, t, og0, og1;
        v0 = __fmul_rn(m1c[0], vld[0]); t = __fmul_rn(__fmul_rn(v0, omx), omy); og0 = t;
        v0 = __fmul_rn(m1c[1], vld[1]); t = __fmul_rn(__fmul_rn(v0, wx),  omy); og0 = __fadd_rn(og0, t);
        v0 = __fmul_rn(m1c[2], vld[2]); t = __fmul_rn(__fmul_rn(v0, omx), wy);  og0 = __fadd_rn(og0, t);
        v0 = __fmul_rn(m1c[3], vld[3]); t = __fmul_rn(__fmul_rn(v0, wx),  wy);  og0 = __fadd_rn(og0, t);
        v0 = __fmul_rn(m2c[0], vld[0]); t = __fmul_rn(__fmul_rn(v0, omx), omy); og1 = t;
        v0 = __fmul_rn(m2c[1], vld[1]); t = __fmul_rn(__fmul_rn(v0, wx),  omy); og1 = __fadd_rn(og1, t);
        v0 = __fmul_rn(m2c[2], vld[2]); t = __fmul_rn(__fmul_rn(v0, omx), wy);  og1 = __fadd_rn(og1, t);
        v0 = __fmul_rn(m2c[3], vld[3]); t = __fmul_rn(__fmul_rn(v0, wx),  wy);  og1 = __fadd_rn(og1, t);
        g_unc[b * KN + p] = -__fadd_rn(og0, -og1);
    }
}

// ------------------------------------------------------------------
// Kernel B: hybrid shfl/smem bitonic (stable top-192) + points out
// ------------------------------------------------------------------
__device__ __forceinline__ unsigned long long bstep(unsigned long long v,
                                                    unsigned long long u,
                                                    int t, int k, int j) {
    bool keep_min = (((t & k) == 0) == ((t & j) == 0));
    unsigned long long mn = v < u ? v : u;
    unsigned long long mx = v < u ? u : v;
    return keep_min ? mn : mx;
}

__global__ void sort_kernel(const float* __restrict__ rand_over,
                            const float* __restrict__ rand_cov,
                            float* __restrict__ dout) {
    __shared__ unsigned long long key[1024];
    int b = blockIdx.x;
    int t = threadIdx.x;

    unsigned long long v = ~0ULL;
    if (t < KN) {
        float u = g_unc[b * KN + t];
        unsigned ub = __float_as_uint(u);
        ub = (ub & 0x80000000u) ? ~ub : (ub | 0x80000000u);
        ub = ~ub;
        v = ((unsigned long long)ub << 32) | (unsigned)t;
    }

#pragma unroll
    for (int k = 2; k <= 32; k <<= 1) {
#pragma unroll
        for (int j = k >> 1; j > 0; j >>= 1) {
            unsigned long long u = __shfl_xor_sync(0xffffffffu, v, j);
            v = bstep(v, u, t, k, j);
        }
    }
    for (int k = 64; k <= 1024; k <<= 1) {
        for (int j = k >> 1; j >= 32; j >>= 1) {
            key[t] = v;
            __syncthreads();
            unsigned long long u = key[t ^ j];
            v = bstep(v, u, t, k, j);
            __syncthreads();
        }
#pragma unroll
        for (int j = 16; j > 0; j >>= 1) {
            unsigned long long u = __shfl_xor_sync(0xffffffffu, v, j);
            v = bstep(v, u, t, k, j);
        }
    }

    float* pts = dout + REND_ELEMS;
    if (t < BETA_N) {
        int idx = (int)(v & 0xFFFFFFFFu);
        g_selidx[b * BETA_N + t] = idx;
        pts[((size_t)b * NPTS + t) * 2 + 0] = rand_over[((size_t)b * KN + idx) * 2 + 0];
        pts[((size_t)b * NPTS + t) * 2 + 1] = rand_over[((size_t)b * KN + idx) * 2 + 1];
    } else if (t < NPTS) {
        int j2 = t - BETA_N;
        pts[((size_t)b * NPTS + t) * 2 + 0] = rand_cov[((size_t)b * NCOV + j2) * 2 + 0];
        pts[((size_t)b * NPTS + t) * 2 + 1] = rand_cov[((size_t)b * NCOV + j2) * 2 + 1];
    }
}

// ------------------------------------------------------------------
// Kernel C: rend. grid (16, 8), block 256.
// smem: wsh[192][128] 96 KB + fshT[16][192] 12 KB.
// ------------------------------------------------------------------
#define TILE 16
#define SMEM_BYTES ((C_FEAT*C_OUT + TILE*C_FEAT) * 4)

__global__ void rend_kernel(const float* __restrict__ res2,
                            const float* __restrict__ bias,
                            float* __restrict__ dout) {
    extern __shared__ float sm[];
    float* wsh  = sm;                    // [c][o]
    float* fshT = sm + C_FEAT * C_OUT;   // [p][c]

    __shared__ int   offB[TILE][4];
    __shared__ float wB[TILE][4];

    int b = blockIdx.y, tile = blockIdx.x;
    bool is_cov = (tile >= 12);
    int tid = threadIdx.x;

    if (!is_cov && tid < TILE) {
        const float* pts = dout + REND_ELEMS + ((size_t)b * NPTS + tile * TILE + tid) * 2;
        float px = pts[0], py = pts[1];
        float gx = px * 512.0f - 0.5f, gy = py * 512.0f - 0.5f;
        float xf = floorf(gx), yf = floorf(gy);
        int x0 = (int)xf, y0 = (int)yf;
        float fx = gx - xf, fy = gy - yf;
#pragma unroll
        for (int j = 0; j < 4; j++) {
            int xi = x0 + (j & 1), yi = y0 + (j >> 1);
            float vv = (xi >= 0 && xi < 512 && yi >= 0 && yi < 512) ? 1.0f : 0.0f;
            offB[tid][j] = min(max(yi, 0), 511) * 512 + min(max(xi, 0), 511);
            wB[tid][j]   = ((j & 1) ? fx : 1.0f - fx) * ((j >> 1) ? fy : 1.0f - fy) * vv;
        }
    }

    // stage weight [c][o] (coalesced float4, conflict-free STS.128)
    {
        const float4* w4 = (const float4*)g_wT;
        float4* d4 = (float4*)wsh;
#pragma unroll
        for (int i = 0; i < 24; i++)
            d4[i * 256 + tid] = __ldg(w4 + i * 256 + tid);
    }
    __syncthreads();

    float4* f4 = (float4*)fshT;                       // [p][c/4] rows of 48
    if (is_cov) {
        // contiguous copy: 16 pts x 192 ch = 768 float4
        const float4* src = (const float4*)(g_covfeat
                          + ((size_t)b * NCOV + (tile - 12) * TILE) * C_FEAT);
#pragma unroll
        for (int i = 0; i < 3; i++)
            f4[i * 256 + tid] = __ldg(src + i * 256 + tid);
    } else {
        const int* sel = g_selidx + b * BETA_N + tile * TILE;
        // coarse: 16 pts x 32 float4, 512 B coalesced bursts
#pragma unroll
        for (int i = 0; i < 2; i++) {
            int v = i * 256 + tid;
            int c4 = v & 31, p = v >> 5;
            const float4* src = (const float4*)(g_coarse
                              + ((size_t)b * KN + __ldg(sel + p)) * C_OUT);
            f4[p * 48 + c4] = __ldg(src + c4);
        }
        // res2 gather: channel-fast lanes, conflict-free STS
#pragma unroll 4
        for (int i = 0; i < 4; i++) {
            int v = i * 256 + tid;
            int c = v & 63, p = v >> 6;
            const float* plane = res2 + (size_t)(b * C_RES + c) * HW_RES;
            float r =        wB[p][0] * __ldg(plane + offB[p][0]);
            r = fmaf(wB[p][1], __ldg(plane + offB[p][1]), r);
            r = fmaf(wB[p][2], __ldg(plane + offB[p][2]), r);
            r = fmaf(wB[p][3], __ldg(plane + offB[p][3]), r);
            fshT[p * C_FEAT + C_OUT + c] = r;
        }
    }
    __syncthreads();

    // GEMV: thread = (o = tid&127, ph = tid>>7 -> 8 points). c-quad tiling.
    int o = tid & 127, ph = tid >> 7;
    float acc[8];
    float bv = __ldg(bias + o);
#pragma unroll
    for (int i = 0; i < 8; i++) acc[i] = bv;

    const float* fp = fshT + ph * 8 * C_FEAT;
#pragma unroll 2
    for (int c = 0; c < C_FEAT; c += 4) {
        float w0 = wsh[(c + 0) * C_OUT + o];
        float w1 = wsh[(c + 1) * C_OUT + o];
        float w2 = wsh[(c + 2) * C_OUT + o];
        float w3 = wsh[(c + 3) * C_OUT + o];
#pragma unroll
        for (int pp = 0; pp < 8; pp++) {
            float4 f = *(const float4*)(fp + pp * C_FEAT + c);   // broadcast LDS.128
            float a = acc[pp];
            a = fmaf(w0, f.x, a);
            a = fmaf(w1, f.y, a);
            a = fmaf(w2, f.z, a);
            a = fmaf(w3, f.w, a);
            acc[pp] = a;
        }
    }

    float* rp = dout + ((size_t)b * C_OUT + o) * NPTS + tile * TILE + ph * 8;
    *(float4*)rp       = make_float4(acc[0], acc[1], acc[2], acc[3]);
    *(float4*)(rp + 4) = make_float4(acc[4], acc[5], acc[6], acc[7]);
}

// ------------------------------------------------------------------
extern "C" void kernel_launch(void* const* d_in, const int* in_sizes, int n_in,
                              void* d_out, int out_size) {
    (void)in_sizes; (void)n_in; (void)out_size;
    const float* res2      = (const float*)d_in[1];
    const float* outp      = (const float*)d_in[2];
    const float* rand_over = (const float*)d_in[3];
    const float* rand_cov  = (const float*)d_in[4];
    const float* weight    = (const float*)d_in[5];
    const float* bias      = (const float*)d_in[6];
    float* dout = (float*)d_out;

    unc_kernel<<<dim3(113, B), 256>>>(outp, res2, rand_over, rand_cov, weight);
    sort_kernel<<<B, 1024>>>(rand_over, rand_cov, dout);

    cudaFuncSetAttribute(rend_kernel, cudaFuncAttributeMaxDynamicSharedMemorySize,
                         SMEM_BYTES);
    rend_kernel<<<dim3(16, B), 256, SMEM_BYTES>>>(res2, bias, dout);
}

// round 6
// speedup vs baseline: 1.8889x; 1.0342x over previous
#include <cuda_runtime.h>

#define B        8
#define KN       768
#define BETA_N   192
#define NCOV     64
#define NPTS     256
#define C_OUT    128
#define HW_OUT   (256*256)
#define C_RES    64
#define HW_RES   (512*512)
#define C_FEAT   192
#define REND_ELEMS (B*C_OUT*NPTS)   // 262144
#define TILE 16

__device__ float g_unc[B * KN];
__device__ float g_coarse[(size_t)B * KN * C_OUT];       // [b][pt][c]
__device__ float g_covfeat[(size_t)B * NCOV * C_FEAT];   // [b][pt][c]
__device__ float g_wT[C_FEAT * C_OUT];                   // [c][o]

// ------------------------------------------------------------------
// Kernel A: grid (113, 8), block 256.
//  x <  96 : uncertainty + cached coarse features (1 warp / point)
//  96..111 : cov-point full feature gather ([b][pt][c] layout)
//  x == 112: (b==0) weight transpose
// ------------------------------------------------------------------
__global__ void unc_kernel(const float* __restrict__ outp,
                           const float* __restrict__ res2,
                           const float* __restrict__ rand_over,
                           const float* __restrict__ rand_cov,
                           const float* __restrict__ weight) {
    int b   = blockIdx.y;
    int bx  = blockIdx.x;
    int tid = threadIdx.x;

    if (bx >= 96) {
        if (bx == 112) {
            if (b != 0) return;
            const float4* w4 = (const float4*)weight;
#pragma unroll
            for (int i = 0; i < 24; i++) {
                int idx = i * 256 + tid;
                int o = idx / 48, rem = idx - o * 48;
                float4 v = __ldg(w4 + idx);
                int cb = rem * 4;
                g_wT[(cb + 0) * C_OUT + o] = v.x;
                g_wT[(cb + 1) * C_OUT + o] = v.y;
                g_wT[(cb + 2) * C_OUT + o] = v.z;
                g_wT[(cb + 3) * C_OUT + o] = v.w;
            }
            return;
        }
        // cov gather: 4 points x 192 channels, channel-fast lanes
        int g = bx - 96;
#pragma unroll
        for (int i = 0; i < 3; i++) {
            int v  = i * 256 + tid;          // 0..767
            int jl = v / C_FEAT;             // 0..3
            int c  = v - jl * C_FEAT;        // 0..191
            int j  = g * 4 + jl;
            float px = __ldg(rand_cov + ((size_t)b * NCOV + j) * 2 + 0);
            float py = __ldg(rand_cov + ((size_t)b * NCOV + j) * 2 + 1);
            const float* plane;
            int H;
            if (c < C_OUT) { plane = outp + (size_t)(b * C_OUT + c) * HW_OUT; H = 256; }
            else           { plane = res2 + (size_t)(b * C_RES + (c - C_OUT)) * HW_RES; H = 512; }
            float gx = px * (float)H - 0.5f, gy = py * (float)H - 0.5f;
            float xf = floorf(gx), yf = floorf(gy);
            int x0 = (int)xf, y0 = (int)yf;
            float fx = gx - xf, fy = gy - yf;
            float r = 0.0f;
#pragma unroll
            for (int q = 0; q < 4; q++) {
                int xi = x0 + (q & 1), yi = y0 + (q >> 1);
                if (xi >= 0 && xi < H && yi >= 0 && yi < H) {
                    float cf = ((q & 1) ? fx : 1.0f - fx) * ((q >> 1) ? fy : 1.0f - fy);
                    r = fmaf(cf, __ldg(plane + (size_t)yi * H + xi), r);
                }
            }
            g_covfeat[((size_t)b * NCOV + j) * C_FEAT + c] = r;
        }
        return;
    }

    int warp = tid >> 5, lane = tid & 31;
    int p = bx * 8 + warp;

    const float* rnd = rand_over + ((size_t)b * KN + p) * 2;
    float px = rnd[0], py = rnd[1];

    float gx = __fadd_rn(__fmul_rn(px, 256.0f), -0.5f);
    float gy = __fadd_rn(__fmul_rn(py, 256.0f), -0.5f);
    float x0f = floorf(gx), y0f = floorf(gy);
    float wx = __fadd_rn(gx, -x0f);
    float wy = __fadd_rn(gy, -y0f);
    int x0 = (int)x0f, y0 = (int)y0f;

    int   pix[4];
    float vld[4];
#pragma unroll
    for (int j = 0; j < 4; j++) {
        int xi = x0 + (j & 1), yi = y0 + (j >> 1);
        vld[j] = (xi >= 0 && xi < 256 && yi >= 0 && yi < 256) ? 1.0f : 0.0f;
        int cx = min(max(xi, 0), 255), cy = min(max(yi, 0), 255);
        pix[j] = cy * 256 + cx;
    }

    const float* ob = outp + (size_t)b * C_OUT * HW_OUT;
    float vals[16];
#pragma unroll
    for (int j = 0; j < 4; j++)
#pragma unroll
        for (int k = 0; k < 4; k++)
            vals[j * 4 + k] = __ldg(ob + (size_t)(lane + k * 32) * HW_OUT + pix[j]);

    {
        float omx = 1.0f - wx, omy = 1.0f - wy;
        float cw[4] = { omx * omy * vld[0], wx * omy * vld[1],
                        omx * wy  * vld[2], wx * wy  * vld[3] };
        float* cc = g_coarse + ((size_t)b * KN + p) * C_OUT + lane;
#pragma unroll
        for (int k = 0; k < 4; k++) {
            float r = vals[k] * cw[0];
            r = fmaf(vals[4 + k],  cw[1], r);
            r = fmaf(vals[8 + k],  cw[2], r);
            r = fmaf(vals[12 + k], cw[3], r);
            cc[k * 32] = r;
        }
    }

    float m1c[4], m2c[4];
#pragma unroll
    for (int j = 0; j < 4; j++) {
        float m1 = vals[j * 4], m2 = -3.4e38f;
#pragma unroll
        for (int k = 1; k < 4; k++) {
            float v  = vals[j * 4 + k];
            float hi = fmaxf(m1, v), lo = fminf(m1, v);
            m2 = fmaxf(m2, lo);
            m1 = hi;
        }
#pragma unroll
        for (int off = 16; off; off >>= 1) {
            float o1 = __shfl_xor_sync(0xffffffffu, m1, off);
            float o2 = __shfl_xor_sync(0xffffffffu, m2, off);
            float hi = fmaxf(m1, o1), lo = fminf(m1, o1);
            m2 = fmaxf(lo, fmaxf(m2, o2));
            m1 = hi;
        }
        m1c[j] = m1; m2c[j] = m2;
    }

    if (lane == 0) {
        float omx = __fadd_rn(1.0f, -wx);
        float omy = __fadd_rn(1.0f, -wy);
        float v0, t, og0, og1;
        v0 = __fmul_rn(m1c[0], vld[0]); t = __fmul_rn(__fmul_rn(v0, omx), omy); og0 = t;
        v0 = __fmul_rn(m1c[1], vld[1]); t = __fmul_rn(__fmul_rn(v0, wx),  omy); og0 = __fadd_rn(og0, t);
        v0 = __fmul_rn(m1c[2], vld[2]); t = __fmul_rn(__fmul_rn(v0, omx), wy);  og0 = __fadd_rn(og0, t);
        v0 = __fmul_rn(m1c[3], vld[3]); t = __fmul_rn(__fmul_rn(v0, wx),  wy);  og0 = __fadd_rn(og0, t);
        v0 = __fmul_rn(m2c[0], vld[0]); t = __fmul_rn(__fmul_rn(v0, omx), omy); og1 = t;
        v0 = __fmul_rn(m2c[1], vld[1]); t = __fmul_rn(__fmul_rn(v0, wx),  omy); og1 = __fadd_rn(og1, t);
        v0 = __fmul_rn(m2c[2], vld[2]); t = __fmul_rn(__fmul_rn(v0, omx), wy);  og1 = __fadd_rn(og1, t);
        v0 = __fmul_rn(m2c[3], vld[3]); t = __fmul_rn(__fmul_rn(v0, wx),  wy);  og1 = __fadd_rn(og1, t);
        g_unc[b * KN + p] = -__fadd_rn(og0, -og1);
    }
}

// ------------------------------------------------------------------
// Kernel B (fused sort+rend): grid (16, 8), block 256.
// imp blocks (tile<12): redundant in-block bitonic top-k, then gather+GEMV.
// cov blocks: straight copy + GEMV.
// smem: wsh 96KB + fshT 12KB + skey 8KB = 116.6 KB
// ------------------------------------------------------------------
#define SMEM_BYTES ((C_FEAT*C_OUT + TILE*C_FEAT) * 4 + 1024 * 8)

__global__ void rend_kernel(const float* __restrict__ res2,
                            const float* __restrict__ rand_over,
                            const float* __restrict__ rand_cov,
                            const float* __restrict__ bias,
                            float* __restrict__ dout) {
    extern __shared__ float sm[];
    float* wsh  = sm;                    // [c][o]
    float* fshT = sm + C_FEAT * C_OUT;   // [p][c]
    unsigned long long* skey = (unsigned long long*)(fshT + TILE * C_FEAT);

    __shared__ int   offB[TILE][4];
    __shared__ float wB[TILE][4];
    __shared__ int   selp[TILE];

    int b = blockIdx.y, tile = blockIdx.x;
    bool is_cov = (tile >= 12);
    int tid = threadIdx.x;

    // ---- stage weight [c][o] (LDGs overlap the sort below) ----
    {
        const float4* w4 = (const float4*)g_wT;
        float4* d4 = (float4*)wsh;
#pragma unroll
        for (int i = 0; i < 24; i++)
            d4[i * 256 + tid] = __ldg(w4 + i * 256 + tid);
    }

    if (!is_cov) {
        // ---- in-block bitonic sort of 768 keys (padded to 1024) ----
#pragma unroll
        for (int i = 0; i < 4; i++) {
            int t = i * 256 + tid;
            unsigned long long v = ~0ULL;
            if (t < KN) {
                float u = g_unc[b * KN + t];
                unsigned ub = __float_as_uint(u);
                ub = (ub & 0x80000000u) ? ~ub : (ub | 0x80000000u);
                ub = ~ub;                                    // descending value
                v = ((unsigned long long)ub << 32) | (unsigned)t;  // tie: asc idx
            }
            skey[t] = v;
        }
        __syncthreads();

        for (int k = 2; k <= 1024; k <<= 1) {
            for (int j = k >> 1; j > 0; j >>= 1) {
#pragma unroll
                for (int q = 0; q < 2; q++) {
                    int pr = q * 256 + tid;                  // 0..511
                    int i  = ((pr & ~(j - 1)) << 1) | (pr & (j - 1));
                    int ix = i | j;
                    unsigned long long a = skey[i], c = skey[ix];
                    bool up = ((i & k) == 0);
                    if ((a > c) == up) { skey[i] = c; skey[ix] = a; }
                }
                __syncthreads();
            }
        }

        // ---- my 16 points: indices, coords out, res2 params ----
        if (tid < TILE) {
            int idx = (int)(skey[tile * TILE + tid] & 0xFFFFFFFFu);
            selp[tid] = idx;
            float px = __ldg(rand_over + ((size_t)b * KN + idx) * 2 + 0);
            float py = __ldg(rand_over + ((size_t)b * KN + idx) * 2 + 1);
            float* pts = dout + REND_ELEMS + ((size_t)b * NPTS + tile * TILE + tid) * 2;
            pts[0] = px; pts[1] = py;

            float gx = px * 512.0f - 0.5f, gy = py * 512.0f - 0.5f;
            float xf = floorf(gx), yf = floorf(gy);
            int x0 = (int)xf, y0 = (int)yf;
            float fx = gx - xf, fy = gy - yf;
#pragma unroll
            for (int j = 0; j < 4; j++) {
                int xi = x0 + (j & 1), yi = y0 + (j >> 1);
                float vv = (xi >= 0 && xi < 512 && yi >= 0 && yi < 512) ? 1.0f : 0.0f;
                offB[tid][j] = min(max(yi, 0), 511) * 512 + min(max(xi, 0), 511);
                wB[tid][j]   = ((j & 1) ? fx : 1.0f - fx) * ((j >> 1) ? fy : 1.0f - fy) * vv;
            }
        }
        __syncthreads();

        // ---- gather features ----
        float4* f4 = (float4*)fshT;                    // [p][c/4], rows of 48
        // coarse: 16 pts x 32 float4 (512 B coalesced bursts)
#pragma unroll
        for (int i = 0; i < 2; i++) {
            int v = i * 256 + tid;
            int c4 = v & 31, p = v >> 5;
            const float4* src = (const float4*)(g_coarse
                              + ((size_t)b * KN + selp[p]) * C_OUT);
            f4[p * 48 + c4] = __ldg(src + c4);
        }
        // res2 gather: channel-fast lanes
#pragma unroll 4
        for (int i = 0; i < 4; i++) {
            int v = i * 256 + tid;
            int c = v & 63, p = v >> 6;
            const float* plane = res2 + (size_t)(b * C_RES + c) * HW_RES;
            float r =        wB[p][0] * __ldg(plane + offB[p][0]);
            r = fmaf(wB[p][1], __ldg(plane + offB[p][1]), r);
            r = fmaf(wB[p][2], __ldg(plane + offB[p][2]), r);
            r = fmaf(wB[p][3], __ldg(plane + offB[p][3]), r);
            fshT[p * C_FEAT + C_OUT + c] = r;
        }
    } else {
        // ---- cov tile: points out + contiguous feature copy ----
        if (tid < TILE) {
            int j2 = (tile - 12) * TILE + tid;
            float px = __ldg(rand_cov + ((size_t)b * NCOV + j2) * 2 + 0);
            float py = __ldg(rand_cov + ((size_t)b * NCOV + j2) * 2 + 1);
            float* pts = dout + REND_ELEMS + ((size_t)b * NPTS + tile * TILE + tid) * 2;
            pts[0] = px; pts[1] = py;
        }
        float4* f4 = (float4*)fshT;
        const float4* src = (const float4*)(g_covfeat
                          + ((size_t)b * NCOV + (tile - 12) * TILE) * C_FEAT);
#pragma unroll
        for (int i = 0; i < 3; i++)
            f4[i * 256 + tid] = __ldg(src + i * 256 + tid);
    }
    __syncthreads();

    // ---- GEMV: thread = (o = tid&127, ph = tid>>7 -> 8 points) ----
    int o = tid & 127, ph = tid >> 7;
    float acc[8];
    float bv = __ldg(bias + o);
#pragma unroll
    for (int i = 0; i < 8; i++) acc[i] = bv;

    const float* fp = fshT + ph * 8 * C_FEAT;
#pragma unroll 2
    for (int c = 0; c < C_FEAT; c += 4) {
        float w0 = wsh[(c + 0) * C_OUT + o];
        float w1 = wsh[(c + 1) * C_OUT + o];
        float w2 = wsh[(c + 2) * C_OUT + o];
        float w3 = wsh[(c + 3) * C_OUT + o];
#pragma unroll
        for (int pp = 0; pp < 8; pp++) {
            float4 f = *(const float4*)(fp + pp * C_FEAT + c);   // broadcast LDS.128
            float a = acc[pp];
            a = fmaf(w0, f.x, a);
            a = fmaf(w1, f.y, a);
            a = fmaf(w2, f.z, a);
            a = fmaf(w3, f.w, a);
            acc[pp] = a;
        }
    }

    float* rp = dout + ((size_t)b * C_OUT + o) * NPTS + tile * TILE + ph * 8;
    *(float4*)rp       = make_float4(acc[0], acc[1], acc[2], acc[3]);
    *(float4*)(rp + 4) = make_float4(acc[4], acc[5], acc[6], acc[7]);
}

// ------------------------------------------------------------------
extern "C" void kernel_launch(void* const* d_in, const int* in_sizes, int n_in,
                              void* d_out, int out_size) {
    (void)in_sizes; (void)n_in; (void)out_size;
    const float* res2      = (const float*)d_in[1];
    const float* outp      = (const float*)d_in[2];
    const float* rand_over = (const float*)d_in[3];
    const float* rand_cov  = (const float*)d_in[4];
    const float* weight    = (const float*)d_in[5];
    const float* bias      = (const float*)d_in[6];
    float* dout = (float*)d_out;

    unc_kernel<<<dim3(113, B), 256>>>(outp, res2, rand_over, rand_cov, weight);

    cudaFuncSetAttribute(rend_kernel, cudaFuncAttributeMaxDynamicSharedMemorySize,
                         SMEM_BYTES);
    rend_kernel<<<dim3(16, B), 256, SMEM_BYTES>>>(res2, rand_over, rand_cov, bias, dout);
}

// round 7
// speedup vs baseline: 1.9568x; 1.0360x over previous
#include <cuda_runtime.h>

#define B        8
#define KN       768
#define BETA_N   192
#define NCOV     64
#define NPTS     256
#define C_OUT    128
#define HW_OUT   (256*256)
#define C_RES    64
#define HW_RES   (512*512)
#define C_FEAT   192
#define REND_ELEMS (B*C_OUT*NPTS)   // 262144
#define TILE 16

typedef unsigned long long ull;

__device__ float g_unc[B * KN];
__device__ float g_coarse[(size_t)B * KN * C_OUT];       // [b][pt][c]
__device__ float g_covfeat[(size_t)B * NCOV * C_FEAT];   // [b][pt][c]
__device__ float g_wT[C_FEAT * C_OUT];                   // [c][o]

// ------------------------------------------------------------------
// Kernel A: grid (113, 8), block 256.
// ------------------------------------------------------------------
__global__ void unc_kernel(const float* __restrict__ outp,
                           const float* __restrict__ res2,
                           const float* __restrict__ rand_over,
                           const float* __restrict__ rand_cov,
                           const float* __restrict__ weight) {
    int b   = blockIdx.y;
    int bx  = blockIdx.x;
    int tid = threadIdx.x;

    if (bx >= 96) {
        if (bx == 112) {
            if (b != 0) return;
            const float4* w4 = (const float4*)weight;
#pragma unroll
            for (int i = 0; i < 24; i++) {
                int idx = i * 256 + tid;
                int o = idx / 48, rem = idx - o * 48;
                float4 v = __ldg(w4 + idx);
                int cb = rem * 4;
                g_wT[(cb + 0) * C_OUT + o] = v.x;
                g_wT[(cb + 1) * C_OUT + o] = v.y;
                g_wT[(cb + 2) * C_OUT + o] = v.z;
                g_wT[(cb + 3) * C_OUT + o] = v.w;
            }
            return;
        }
        int g = bx - 96;
#pragma unroll
        for (int i = 0; i < 3; i++) {
            int v  = i * 256 + tid;
            int jl = v / C_FEAT;
            int c  = v - jl * C_FEAT;
            int j  = g * 4 + jl;
            float px = __ldg(rand_cov + ((size_t)b * NCOV + j) * 2 + 0);
            float py = __ldg(rand_cov + ((size_t)b * NCOV + j) * 2 + 1);
            const float* plane;
            int H;
            if (c < C_OUT) { plane = outp + (size_t)(b * C_OUT + c) * HW_OUT; H = 256; }
            else           { plane = res2 + (size_t)(b * C_RES + (c - C_OUT)) * HW_RES; H = 512; }
            float gx = px * (float)H - 0.5f, gy = py * (float)H - 0.5f;
            float xf = floorf(gx), yf = floorf(gy);
            int x0 = (int)xf, y0 = (int)yf;
            float fx = gx - xf, fy = gy - yf;
            float r = 0.0f;
#pragma unroll
            for (int q = 0; q < 4; q++) {
                int xi = x0 + (q & 1), yi = y0 + (q >> 1);
                if (xi >= 0 && xi < H && yi >= 0 && yi < H) {
                    float cf = ((q & 1) ? fx : 1.0f - fx) * ((q >> 1) ? fy : 1.0f - fy);
                    r = fmaf(cf, __ldg(plane + (size_t)yi * H + xi), r);
                }
            }
            g_covfeat[((size_t)b * NCOV + j) * C_FEAT + c] = r;
        }
        return;
    }

    int warp = tid >> 5, lane = tid & 31;
    int p = bx * 8 + warp;

    const float* rnd = rand_over + ((size_t)b * KN + p) * 2;
    float px = rnd[0], py = rnd[1];

    float gx = __fadd_rn(__fmul_rn(px, 256.0f), -0.5f);
    float gy = __fadd_rn(__fmul_rn(py, 256.0f), -0.5f);
    float x0f = floorf(gx), y0f = floorf(gy);
    float wx = __fadd_rn(gx, -x0f);
    float wy = __fadd_rn(gy, -y0f);
    int x0 = (int)x0f, y0 = (int)y0f;

    int   pix[4];
    float vld[4];
#pragma unroll
    for (int j = 0; j < 4; j++) {
        int xi = x0 + (j & 1), yi = y0 + (j >> 1);
        vld[j] = (xi >= 0 && xi < 256 && yi >= 0 && yi < 256) ? 1.0f : 0.0f;
        int cx = min(max(xi, 0), 255), cy = min(max(yi, 0), 255);
        pix[j] = cy * 256 + cx;
    }

    const float* ob = outp + (size_t)b * C_OUT * HW_OUT;
    float vals[16];
#pragma unroll
    for (int j = 0; j < 4; j++)
#pragma unroll
        for (int k = 0; k < 4; k++)
            vals[j * 4 + k] = __ldg(ob + (size_t)(lane + k * 32) * HW_OUT + pix[j]);

    {
        float omx = 1.0f - wx, omy = 1.0f - wy;
        float cw[4] = { omx * omy * vld[0], wx * omy * vld[1],
                        omx * wy  * vld[2], wx * wy  * vld[3] };
        float* cc = g_coarse + ((size_t)b * KN + p) * C_OUT + lane;
#pragma unroll
        for (int k = 0; k < 4; k++) {
            float r = vals[k] * cw[0];
            r = fmaf(vals[4 + k],  cw[1], r);
            r = fmaf(vals[8 + k],  cw[2], r);
            r = fmaf(vals[12 + k], cw[3], r);
            cc[k * 32] = r;
        }
    }

    float m1c[4], m2c[4];
#pragma unroll
    for (int j = 0; j < 4; j++) {
        float m1 = vals[j * 4], m2 = -3.4e38f;
#pragma unroll
        for (int k = 1; k < 4; k++) {
            float v  = vals[j * 4 + k];
            float hi = fmaxf(m1, v), lo = fminf(m1, v);
            m2 = fmaxf(m2, lo);
            m1 = hi;
        }
#pragma unroll
        for (int off = 16; off; off >>= 1) {
            float o1 = __shfl_xor_sync(0xffffffffu, m1, off);
            float o2 = __shfl_xor_sync(0xffffffffu, m2, off);
            float hi = fmaxf(m1, o1), lo = fminf(m1, o1);
            m2 = fmaxf(lo, fmaxf(m2, o2));
            m1 = hi;
        }
        m1c[j] = m1; m2c[j] = m2;
    }

    if (lane == 0) {
        float omx = __fadd_rn(1.0f, -wx);
        float omy = __fadd_rn(1.0f, -wy);
        float v0, t, og0, og1;
        v0 = __fmul_rn(m1c[0], vld[0]); t = __fmul_rn(__fmul_rn(v0, omx), omy); og0 = t;
        v0 = __fmul_rn(m1c[1], vld[1]); t = __fmul_rn(__fmul_rn(v0, wx),  omy); og0 = __fadd_rn(og0, t);
        v0 = __fmul_rn(m1c[2], vld[2]); t = __fmul_rn(__fmul_rn(v0, omx), wy);  og0 = __fadd_rn(og0, t);
        v0 = __fmul_rn(m1c[3], vld[3]); t = __fmul_rn(__fmul_rn(v0, wx),  wy);  og0 = __fadd_rn(og0, t);
        v0 = __fmul_rn(m2c[0], vld[0]); t = __fmul_rn(__fmul_rn(v0, omx), omy); og1 = t;
        v0 = __fmul_rn(m2c[1], vld[1]); t = __fmul_rn(__fmul_rn(v0, wx),  omy); og1 = __fadd_rn(og1, t);
        v0 = __fmul_rn(m2c[2], vld[2]); t = __fmul_rn(__fmul_rn(v0, omx), wy);  og1 = __fadd_rn(og1, t);
        v0 = __fmul_rn(m2c[3], vld[3]); t = __fmul_rn(__fmul_rn(v0, wx),  wy);  og1 = __fadd_rn(og1, t);
        g_unc[b * KN + p] = -__fadd_rn(og0, -og1);
    }
}

// ------------------------------------------------------------------
// Kernel B (fused sort+rend): grid (16, 8), block 256.
// Register/shfl bitonic: 4 keys/thread, only j>=128 steps touch smem.
// ------------------------------------------------------------------
#define SMEM_BYTES ((C_FEAT*C_OUT + TILE*C_FEAT) * 4 + 1024 * 8)

__device__ __forceinline__ void cxr(ull& a, ull& b, bool up) {
    ull mn = a < b ? a : b;
    ull mx = a < b ? b : a;
    a = up ? mn : mx;
    b = up ? mx : mn;
}

__global__ void rend_kernel(const float* __restrict__ res2,
                            const float* __restrict__ rand_over,
                            const float* __restrict__ rand_cov,
                            const float* __restrict__ bias,
                            float* __restrict__ dout) {
    extern __shared__ float sm[];
    float* wsh  = sm;                    // [c][o]  96 KB
    float* fshT = sm + C_FEAT * C_OUT;   // [p][c]  12 KB
    ull*   skey = (ull*)(fshT + TILE * C_FEAT);   // 8 KB

    __shared__ int   offB[TILE][4];
    __shared__ float wB[TILE][4];
    __shared__ int   selall[256];

    int b = blockIdx.y, tile = blockIdx.x;
    bool is_cov = (tile >= 12);
    int tid = threadIdx.x;

    // ---- stage weight (LDGs overlap the sort) ----
    {
        const float4* w4 = (const float4*)g_wT;
        float4* d4 = (float4*)wsh;
#pragma unroll
        for (int i = 0; i < 24; i++)
            d4[i * 256 + tid] = __ldg(w4 + i * 256 + tid);
    }

    if (!is_cov) {
        // ---- load 4 keys/thread (element i = 4*tid + r) ----
        ull v[4];
        int base = tid * 4;
        if (base < KN) {
            float4 u4 = *(const float4*)(g_unc + b * KN + base);
            float uu[4] = { u4.x, u4.y, u4.z, u4.w };
#pragma unroll
            for (int r = 0; r < 4; r++) {
                unsigned ub = __float_as_uint(uu[r]);
                ub = (ub & 0x80000000u) ? ~ub : (ub | 0x80000000u);
                ub = ~ub;                                   // descending value
                v[r] = ((ull)ub << 32) | (unsigned)(base + r);  // tie: asc idx
            }
        } else {
#pragma unroll
            for (int r = 0; r < 4; r++) v[r] = ~0ULL;
        }

        // ---- bitonic network on 1024 elements ----
        // k = 2
        cxr(v[0], v[1], true);
        cxr(v[2], v[3], false);
        // k = 4
        {
            bool up = ((tid & 1) == 0);
            cxr(v[0], v[2], up); cxr(v[1], v[3], up);
            cxr(v[0], v[1], up); cxr(v[2], v[3], up);
        }
        // k = 8 .. 1024
        for (int k = 8; k <= 1024; k <<= 1) {
            bool up = ((tid & (k >> 2)) == 0);
            for (int j = k >> 1; j >= 4; j >>= 1) {
                int d = j >> 2;                     // thread distance
                if (d <= 16) {
                    // intra-warp shfl step
                    bool keep_min = (((tid & d) == 0) == up);
#pragma unroll
                    for (int r = 0; r < 4; r++) {
                        ull u = __shfl_xor_sync(0xffffffffu, v[r], d);
                        ull mn = v[r] < u ? v[r] : u;
                        ull mx = v[r] < u ? u : v[r];
                        v[r] = keep_min ? mn : mx;
                    }
                } else {
                    // cross-warp smem step
#pragma unroll
                    for (int r = 0; r < 4; r++) skey[tid * 4 + r] = v[r];
                    __syncthreads();
                    bool keep_min = (((tid & d) == 0) == up);
                    int pt = (tid ^ d) * 4;
#pragma unroll
                    for (int r = 0; r < 4; r++) {
                        ull u = skey[pt + r];
                        ull mn = v[r] < u ? v[r] : u;
                        ull mx = v[r] < u ? u : v[r];
                        v[r] = keep_min ? mn : mx;
                    }
                    __syncthreads();
                }
            }
            // j = 2, 1: register-local
            cxr(v[0], v[2], up); cxr(v[1], v[3], up);
            cxr(v[0], v[1], up); cxr(v[2], v[3], up);
        }

        // ---- publish top-256 indices ----
        if (tid < 64) {
#pragma unroll
            for (int r = 0; r < 4; r++)
                selall[tid * 4 + r] = (int)(v[r] & 0xFFFFFFFFu);
        }
        __syncthreads();

        // ---- my 16 points: coords out + res2 params ----
        if (tid < TILE) {
            int idx = selall[tile * TILE + tid];
            float px = __ldg(rand_over + ((size_t)b * KN + idx) * 2 + 0);
            float py = __ldg(rand_over + ((size_t)b * KN + idx) * 2 + 1);
            float* pts = dout + REND_ELEMS + ((size_t)b * NPTS + tile * TILE + tid) * 2;
            pts[0] = px; pts[1] = py;

            float gx = px * 512.0f - 0.5f, gy = py * 512.0f - 0.5f;
            float xf = floorf(gx), yf = floorf(gy);
            int x0 = (int)xf, y0 = (int)yf;
            float fx = gx - xf, fy = gy - yf;
#pragma unroll
            for (int j = 0; j < 4; j++) {
                int xi = x0 + (j & 1), yi = y0 + (j >> 1);
                float vv = (xi >= 0 && xi < 512 && yi >= 0 && yi < 512) ? 1.0f : 0.0f;
                offB[tid][j] = min(max(yi, 0), 511) * 512 + min(max(xi, 0), 511);
                wB[tid][j]   = ((j & 1) ? fx : 1.0f - fx) * ((j >> 1) ? fy : 1.0f - fy) * vv;
            }
        }
        __syncthreads();

        // ---- gather features ----
        float4* f4 = (float4*)fshT;                    // [p][c/4], rows of 48
#pragma unroll
        for (int i = 0; i < 2; i++) {
            int vv = i * 256 + tid;
            int c4 = vv & 31, p = vv >> 5;
            const float4* src = (const float4*)(g_coarse
                              + ((size_t)b * KN + selall[tile * TILE + p]) * C_OUT);
            f4[p * 48 + c4] = __ldg(src + c4);
        }
#pragma unroll 4
        for (int i = 0; i < 4; i++) {
            int vv = i * 256 + tid;
            int c = vv & 63, p = vv >> 6;
            const float* plane = res2 + (size_t)(b * C_RES + c) * HW_RES;
            float r =        wB[p][0] * __ldg(plane + offB[p][0]);
            r = fmaf(wB[p][1], __ldg(plane + offB[p][1]), r);
            r = fmaf(wB[p][2], __ldg(plane + offB[p][2]), r);
            r = fmaf(wB[p][3], __ldg(plane + offB[p][3]), r);
            fshT[p * C_FEAT + C_OUT + c] = r;
        }
    } else {
        // ---- cov tile ----
        if (tid < TILE) {
            int j2 = (tile - 12) * TILE + tid;
            float px = __ldg(rand_cov + ((size_t)b * NCOV + j2) * 2 + 0);
            float py = __ldg(rand_cov + ((size_t)b * NCOV + j2) * 2 + 1);
            float* pts = dout + REND_ELEMS + ((size_t)b * NPTS + tile * TILE + tid) * 2;
            pts[0] = px; pts[1] = py;
        }
        float4* f4 = (float4*)fshT;
        const float4* src = (const float4*)(g_covfeat
                          + ((size_t)b * NCOV + (tile - 12) * TILE) * C_FEAT);
#pragma unroll
        for (int i = 0; i < 3; i++)
            f4[i * 256 + tid] = __ldg(src + i * 256 + tid);
    }
    __syncthreads();

    // ---- GEMV ----
    int o = tid & 127, ph = tid >> 7;
    float acc[8];
    float bv = __ldg(bias + o);
#pragma unroll
    for (int i = 0; i < 8; i++) acc[i] = bv;

    const float* fp = fshT + ph * 8 * C_FEAT;
#pragma unroll 2
    for (int c = 0; c < C_FEAT; c += 4) {
        float w0 = wsh[(c + 0) * C_OUT + o];
        float w1 = wsh[(c + 1) * C_OUT + o];
        float w2 = wsh[(c + 2) * C_OUT + o];
        float w3 = wsh[(c + 3) * C_OUT + o];
#pragma unroll
        for (int pp = 0; pp < 8; pp++) {
            float4 f = *(const float4*)(fp + pp * C_FEAT + c);
            float a = acc[pp];
            a = fmaf(w0, f.x, a);
            a = fmaf(w1, f.y, a);
            a = fmaf(w2, f.z, a);
            a = fmaf(w3, f.w, a);
            acc[pp] = a;
        }
    }

    float* rp = dout + ((size_t)b * C_OUT + o) * NPTS + tile * TILE + ph * 8;
    *(float4*)rp       = make_float4(acc[0], acc[1], acc[2], acc[3]);
    *(float4*)(rp + 4) = make_float4(acc[4], acc[5], acc[6], acc[7]);
}

// ------------------------------------------------------------------
extern "C" void kernel_launch(void* const* d_in, const int* in_sizes, int n_in,
                              void* d_out, int out_size) {
    (void)in_sizes; (void)n_in; (void)out_size;
    const float* res2      = (const float*)d_in[1];
    const float* outp      = (const float*)d_in[2];
    const float* rand_over = (const float*)d_in[3];
    const float* rand_cov  = (const float*)d_in[4];
    const float* weight    = (const float*)d_in[5];
    const float* bias      = (const float*)d_in[6];
    float* dout = (float*)d_out;

    unc_kernel<<<dim3(113, B), 256>>>(outp, res2, rand_over, rand_cov, weight);

    cudaFuncSetAttribute(rend_kernel, cudaFuncAttributeMaxDynamicSharedMemorySize,
                         SMEM_BYTES);
    rend_kernel<<<dim3(16, B), 256, SMEM_BYTES>>>(res2, rand_over, rand_cov, bias, dout);
}